// round 17
// baseline (speedup 1.0000x reference)
#include <cuda_runtime.h>
#include <cuda_fp16.h>

// DenseGATBlock: 2-layer GAT, N=8192, D=128, heads=1, sparse adj (~1% + self loops).
// R14: 2 warps per row in aggregate (halved serial gather chain, 3 cheap block
//      barriers for the cross-half handshake). Rest identical to passing R13.

#define NN 8192
#define DD 128
#define MAXDEG 256
#define BM 32
#define GEMM_BLOCKS (NN / BM)   // 256

// Scratch (device globals; no allocation allowed)
__device__ int   g_col[NN * MAXDEG];              // 8 MB padded neighbor lists
__device__ int   g_deg[NN];
__device__ __align__(16) __half g_h16[NN * DD];   // 2 MB, L2-resident
__device__ float g_asrc[NN];
__device__ float g_adst[NN];

// ---------------------------------------------------------------------------
// CSR build body: one block per row, 256 threads, prefetch 8 float4/thread.
// ---------------------------------------------------------------------------
__device__ __forceinline__ void csr_body(const float* __restrict__ adj, int i) {
    __shared__ int cnt;
    if (threadIdx.x == 0) cnt = 0;
    __syncthreads();
    const float4* row = (const float4*)(adj + (size_t)i * NN);
    int* outc = g_col + i * MAXDEG;
    int tid = threadIdx.x;

    float4 f[8];
#pragma unroll
    for (int k = 0; k < 8; k++) f[k] = __ldcs(&row[tid + k * 256]);   // MLP=8, streaming

#pragma unroll
    for (int k = 0; k < 8; k++) {
        int base = 4 * (tid + k * 256);
        if (f[k].x != 0.f) { int p = atomicAdd(&cnt, 1); if (p < MAXDEG) outc[p] = base; }
        if (f[k].y != 0.f) { int p = atomicAdd(&cnt, 1); if (p < MAXDEG) outc[p] = base + 1; }
        if (f[k].z != 0.f) { int p = atomicAdd(&cnt, 1); if (p < MAXDEG) outc[p] = base + 2; }
        if (f[k].w != 0.f) { int p = atomicAdd(&cnt, 1); if (p < MAXDEG) outc[p] = base + 3; }
    }
    __syncthreads();
    if (threadIdx.x == 0) g_deg[i] = cnt < MAXDEG ? cnt : MAXDEG;
}

// ---------------------------------------------------------------------------
// GEMM body: tile = A@W (fp32 compute), 256 threads, 4x4 register tile.
// Epilogue: fused fp32 attention scores + fp16 h store.
// ---------------------------------------------------------------------------
#define BK 32
__device__ __forceinline__ void gemm_body(const float* __restrict__ A,
                                          const float* __restrict__ W,
                                          const float* __restrict__ att_src,
                                          const float* __restrict__ att_dst,
                                          int rowBase) {
    __shared__ __align__(16) float As[BM][BK];   // 4 KB
    __shared__ __align__(16) float Bs[BK][DD];   // 16 KB
    int tid = threadIdx.x;
    int trow = (tid >> 5) * 4;     // warp -> 4 rows (uniform across warp)
    int tcol = tid & 31;           // 0..31 -> 4 cols
    float acc[4][4];
#pragma unroll
    for (int a = 0; a < 4; a++)
#pragma unroll
        for (int b = 0; b < 4; b++) acc[a][b] = 0.f;

    for (int k0 = 0; k0 < DD; k0 += BK) {
        {
            int r = tid >> 3, cc = (tid & 7) * 4;
            *(float4*)&As[r][cc] =
                *(const float4*)&A[(size_t)(rowBase + r) * DD + k0 + cc];
        }
#pragma unroll
        for (int v = 0; v < 4; v++) {
            int ff = tid + 256 * v;
            int r = ff >> 5, cc = (ff & 31) * 4;
            *(float4*)&Bs[r][cc] = *(const float4*)&W[(k0 + r) * DD + cc];
        }
        __syncthreads();
#pragma unroll
        for (int kk = 0; kk < BK; kk++) {
            float a[4];
#pragma unroll
            for (int ii = 0; ii < 4; ii++) a[ii] = As[trow + ii][kk];
            float4 bv = *(float4*)&Bs[kk][tcol * 4];
#pragma unroll
            for (int ii = 0; ii < 4; ii++) {
                acc[ii][0] += a[ii] * bv.x;
                acc[ii][1] += a[ii] * bv.y;
                acc[ii][2] += a[ii] * bv.z;
                acc[ii][3] += a[ii] * bv.w;
            }
        }
        __syncthreads();
    }

    // write h tile as fp16 (4 halves = 8B per thread-row)
#pragma unroll
    for (int ii = 0; ii < 4; ii++) {
        __half2 lo = __floats2half2_rn(acc[ii][0], acc[ii][1]);
        __half2 hi = __floats2half2_rn(acc[ii][2], acc[ii][3]);
        uint2 pk;
        pk.x = *(unsigned*)&lo;
        pk.y = *(unsigned*)&hi;
        *(uint2*)&g_h16[(size_t)(rowBase + trow + ii) * DD + tcol * 4] = pk;
    }

    // fused fp32 attention scores (scalar att loads: alignment-safe)
    float as0 = att_src[tcol * 4 + 0], as1 = att_src[tcol * 4 + 1];
    float as2 = att_src[tcol * 4 + 2], as3 = att_src[tcol * 4 + 3];
    float ad0 = att_dst[tcol * 4 + 0], ad1 = att_dst[tcol * 4 + 1];
    float ad2 = att_dst[tcol * 4 + 2], ad3 = att_dst[tcol * 4 + 3];
#pragma unroll
    for (int ii = 0; ii < 4; ii++) {
        float s = acc[ii][0] * as0 + acc[ii][1] * as1 +
                  acc[ii][2] * as2 + acc[ii][3] * as3;
        float d = acc[ii][0] * ad0 + acc[ii][1] * ad1 +
                  acc[ii][2] * ad2 + acc[ii][3] * ad3;
#pragma unroll
        for (int o = 16; o; o >>= 1) {
            s += __shfl_xor_sync(0xffffffffu, s, o);
            d += __shfl_xor_sync(0xffffffffu, d, o);
        }
        if (tcol == 0) {
            int row = rowBase + trow + ii;
            g_asrc[row] = s;
            g_adst[row] = d;
        }
    }
}

// Fused kernel: blocks [0,256) GEMM tiles, blocks [256, 256+8192) CSR rows.
__global__ void fused_csr_gemm_k(const float* __restrict__ adj,
                                 const float* __restrict__ A,
                                 const float* __restrict__ W,
                                 const float* __restrict__ att_src,
                                 const float* __restrict__ att_dst) {
    if (blockIdx.x < GEMM_BLOCKS)
        gemm_body(A, W, att_src, att_dst, blockIdx.x * BM);
    else
        csr_body(adj, blockIdx.x - GEMM_BLOCKS);
}

// Layer-1 GEMM (CSR already built)
__global__ void gemm_k(const float* __restrict__ A, const float* __restrict__ W,
                       const float* __restrict__ att_src,
                       const float* __restrict__ att_dst) {
    gemm_body(A, W, att_src, att_dst, blockIdx.x * BM);
}

// ---------------------------------------------------------------------------
// Aggregate: 2 WARPS PER ROW. 256 threads = 8 warps = 4 rows per block.
// Each warp of a pair scores+gathers half the edges (serial chain halved);
// cross-half max/sum/partial combined through shared with 3 block barriers.
// Lane owns channels [4*lane, 4*lane+4). Grid = NN/4.
// ---------------------------------------------------------------------------
__global__ __launch_bounds__(256, 8)
void aggregate_k(const float* __restrict__ bias,
                 float* __restrict__ out, int doRelu) {
    __shared__ float s_w[4][MAXDEG];              // 4 KB
    __shared__ int   s_c[4][MAXDEG];              // 4 KB
    __shared__ float s_max[4][2], s_sum[4][2];
    __shared__ __align__(16) float4 s_part[4][32];  // 2 KB (half 1 partials)

    int warp = threadIdx.x >> 5;       // 0..7
    int lane = threadIdx.x & 31;
    int slot = warp >> 1;              // 0..3  (row slot)
    int half = warp & 1;               // 0/1   (edge-list half)
    int i = blockIdx.x * 4 + slot;

    int deg = g_deg[i];
    float adsti = g_adst[i];
    float* swp = s_w[slot];
    int*   scp = s_c[slot];

    // Phase A1: score own stripe (warp h covers j in [64k + 32h, 64k + 32h + 32))
    float m = -1e30f;
    for (int j = half * 32 + lane; j < deg; j += 64) {
        int c = g_col[i * MAXDEG + j];
        float e = g_asrc[c] + adsti;
        e = (e >= 0.f) ? e : 0.2f * e;
        scp[j] = c;
        swp[j] = e;
        m = fmaxf(m, e);
    }
#pragma unroll
    for (int o = 16; o; o >>= 1) m = fmaxf(m, __shfl_xor_sync(0xffffffffu, m, o));
    if (lane == 0) s_max[slot][half] = m;
    __syncthreads();

    // Phase A2: exp over own stripe with global max, partial sum
    m = fmaxf(s_max[slot][0], s_max[slot][1]);
    float sum = 0.f;
    for (int j = half * 32 + lane; j < deg; j += 64) {
        float w = __expf(swp[j] - m);
        swp[j] = w;
        sum += w;
    }
#pragma unroll
    for (int o = 16; o; o >>= 1) sum += __shfl_xor_sync(0xffffffffu, sum, o);
    if (lane == 0) s_sum[slot][half] = sum;
    __syncthreads();          // also orders all swp writes before gather reads
    float inv = 1.0f / (s_sum[slot][0] + s_sum[slot][1]);

    // Phase B: gather own half (interleaved j = half + 2k), 2 indep accumulators
    float4 a0 = make_float4(0.f, 0.f, 0.f, 0.f);
    float4 a1 = make_float4(0.f, 0.f, 0.f, 0.f);
    int j = half;
    for (; j + 2 < deg; j += 4) {
        float w0 = swp[j], w1 = swp[j + 2];
        int   c0 = scp[j], c1 = scp[j + 2];
        uint2 r0 = *(const uint2*)&g_h16[(size_t)c0 * DD + lane * 4];
        uint2 r1 = *(const uint2*)&g_h16[(size_t)c1 * DD + lane * 4];
        float2 f0a = __half22float2(*(__half2*)&r0.x);
        float2 f0b = __half22float2(*(__half2*)&r0.y);
        float2 f1a = __half22float2(*(__half2*)&r1.x);
        float2 f1b = __half22float2(*(__half2*)&r1.y);
        a0.x += w0 * f0a.x; a0.y += w0 * f0a.y; a0.z += w0 * f0b.x; a0.w += w0 * f0b.y;
        a1.x += w1 * f1a.x; a1.y += w1 * f1a.y; a1.z += w1 * f1b.x; a1.w += w1 * f1b.y;
    }
    if (j < deg) {
        float w0 = swp[j];
        uint2 r0 = *(const uint2*)&g_h16[(size_t)scp[j] * DD + lane * 4];
        float2 f0a = __half22float2(*(__half2*)&r0.x);
        float2 f0b = __half22float2(*(__half2*)&r0.y);
        a0.x += w0 * f0a.x; a0.y += w0 * f0a.y; a0.z += w0 * f0b.x; a0.w += w0 * f0b.y;
    }
    a0.x += a1.x; a0.y += a1.y; a0.z += a1.z; a0.w += a1.w;

    if (half == 1) s_part[slot][lane] = a0;
    __syncthreads();

    if (half == 0) {
        float4 p = s_part[slot][lane];
        float b0v = bias[lane * 4 + 0], b1v = bias[lane * 4 + 1];
        float b2v = bias[lane * 4 + 2], b3v = bias[lane * 4 + 3];
        float4 o;
        o.x = (a0.x + p.x) * inv + b0v;
        o.y = (a0.y + p.y) * inv + b1v;
        o.z = (a0.z + p.z) * inv + b2v;
        o.w = (a0.w + p.w) * inv + b3v;
        if (doRelu) {
            o.x = fmaxf(o.x, 0.f); o.y = fmaxf(o.y, 0.f);
            o.z = fmaxf(o.z, 0.f); o.w = fmaxf(o.w, 0.f);
        }
        *(float4*)&out[(size_t)i * DD + lane * 4] = o;
    }
}

// ---------------------------------------------------------------------------
extern "C" void kernel_launch(void* const* d_in, const int* in_sizes, int n_in,
                              void* d_out, int out_size) {
    const float* x        = (const float*)d_in[0];
    const float* adj      = (const float*)d_in[1];
    const float* W0       = (const float*)d_in[2];
    const float* att_src0 = (const float*)d_in[3];
    const float* att_dst0 = (const float*)d_in[4];
    const float* b0       = (const float*)d_in[5];
    const float* W1       = (const float*)d_in[6];
    const float* att_src1 = (const float*)d_in[7];
    const float* att_dst1 = (const float*)d_in[8];
    const float* b1       = (const float*)d_in[9];

    float* out0 = (float*)d_out;                  // [N,128]
    float* out1 = (float*)d_out + (size_t)NN * DD;

    // Layer 0: CSR build (DRAM-bound, MLP=8) overlapped with GEMM
    fused_csr_gemm_k<<<GEMM_BLOCKS + NN, 256>>>(adj, x, W0, att_src0, att_dst0);
    aggregate_k<<<NN / 4, 256>>>(b0, out0, /*relu=*/1);

    // Layer 1
    gemm_k<<<GEMM_BLOCKS, 256>>>(out0, W1, att_src1, att_dst1);
    aggregate_k<<<NN / 4, 256>>>(b1, out1, /*relu=*/0);
}